// round 12
// baseline (speedup 1.0000x reference)
#include <cuda_runtime.h>
#include <cuda_bf16.h>
#include <cstdint>
#include <cstddef>
#include <math.h>

// Problem constants
#define BSZ   16384
#define FDIM  1024
#define HDIM  64
#define DDIM  256
#define NEXP  4
#define NH    256
#define BD    (BSZ * DDIM)

// ---------------------------------------------------------------------------
// Scratch (device globals — no allocation allowed)
// ---------------------------------------------------------------------------
__device__ float g_gA[BSZ * 8];
__device__ float g_gS[BSZ * 12];
__device__ float g_gB[BSZ * 8];

// bf16-split W1, transposed to [N=256][K=1024] rows
__device__ __align__(16) __nv_bfloat16 g_wh[3][256 * 1024];
__device__ __align__(16) __nv_bfloat16 g_wl[3][256 * 1024];
// bf16-split activations [B][1024]
__device__ __align__(16) __nv_bfloat16 g_xh[3][(size_t)BSZ * FDIM];
__device__ __align__(16) __nv_bfloat16 g_xl[3][(size_t)BSZ * FDIM];
// bf16-split hidden h [B][256] per group
__device__ __align__(16) __nv_bfloat16 g_hh[3][(size_t)BSZ * NH];
__device__ __align__(16) __nv_bfloat16 g_hl[3][(size_t)BSZ * NH];
// bf16-split W2 transposed: [z][e][D=256 rows][H=64 cols]
__device__ __align__(16) __nv_bfloat16 g_w2h[12][256 * 64];
__device__ __align__(16) __nv_bfloat16 g_w2l[12][256 * 64];

// ---------------------------------------------------------------------------
// Helpers
// ---------------------------------------------------------------------------
__device__ __forceinline__ uint32_t smem_u32(const void* p) {
    uint32_t a;
    asm("{ .reg .u64 t; cvta.to.shared.u64 t, %1; cvt.u32.u64 %0, t; }" : "=r"(a) : "l"(p));
    return a;
}
__device__ __forceinline__ void cp16(uint32_t dst, const void* src) {
    asm volatile("cp.async.cg.shared.global [%0], [%1], 16;" :: "r"(dst), "l"(src));
}
__device__ __forceinline__ void cp_commit() { asm volatile("cp.async.commit_group;" ::: "memory"); }
template <int N>
__device__ __forceinline__ void cp_wait() { asm volatile("cp.async.wait_group %0;" :: "n"(N) : "memory"); }

__device__ __forceinline__ void ldsm4(uint32_t* r, uint32_t addr) {
    asm volatile("ldmatrix.sync.aligned.m8n8.x4.shared.b16 {%0,%1,%2,%3}, [%4];"
                 : "=r"(r[0]), "=r"(r[1]), "=r"(r[2]), "=r"(r[3]) : "r"(addr));
}
__device__ __forceinline__ void mma16816(float* d, const uint32_t* a, const uint32_t* b) {
    asm volatile(
        "mma.sync.aligned.m16n8k16.row.col.f32.bf16.bf16.f32 "
        "{%0,%1,%2,%3}, {%4,%5,%6,%7}, {%8,%9}, {%0,%1,%2,%3};"
        : "+f"(d[0]), "+f"(d[1]), "+f"(d[2]), "+f"(d[3])
        : "r"(a[0]), "r"(a[1]), "r"(a[2]), "r"(a[3]), "r"(b[0]), "r"(b[1]));
}
__device__ __forceinline__ uint32_t packbf(float x, float y) {
    __nv_bfloat16 hx = __float2bfloat16(x);
    __nv_bfloat16 hy = __float2bfloat16(y);
    return ((uint32_t)__bfloat16_as_ushort(hy) << 16) | __bfloat16_as_ushort(hx);
}
__device__ __forceinline__ void split2(float x, float y, uint32_t& h, uint32_t& l) {
    h = packbf(x, y);
    float rx = x - __bfloat162float(__ushort_as_bfloat16((uint16_t)(h & 0xffff)));
    float ry = y - __bfloat162float(__ushort_as_bfloat16((uint16_t)(h >> 16)));
    l = packbf(rx, ry);
}

// ---------------------------------------------------------------------------
// wsplit: W1 [E,F,H] -> transposed [256][1024] hi/lo bf16
// ---------------------------------------------------------------------------
__global__ __launch_bounds__(256) void wsplit_kernel(
    const float* __restrict__ W1A, const float* __restrict__ W1S, const float* __restrict__ W1B)
{
    int id = blockIdx.x * 256 + threadIdx.x;
    int z = id >> 18;
    int r = id & 262143;
    int c = r >> 10, f = r & 1023;
    const float* W = (z == 0) ? W1A : (z == 1) ? W1S : W1B;
    float v = W[(size_t)(c >> 6) * 65536 + f * 64 + (c & 63)];
    __nv_bfloat16 h = __float2bfloat16(v);
    g_wh[z][c * 1024 + f] = h;
    g_wl[z][c * 1024 + f] = __float2bfloat16(v - __bfloat162float(h));
}

// w2split: W2 [E,H,D] -> [z*4+e][D=256 rows][H=64 cols] hi/lo bf16
__global__ __launch_bounds__(256) void w2split_kernel(
    const float* __restrict__ W2A, const float* __restrict__ W2S, const float* __restrict__ W2B)
{
    int id = blockIdx.x * 256 + threadIdx.x;  // 0..196607
    int z = id >> 16;
    int rem = id & 65535;
    int e = rem >> 14;
    int rem2 = rem & 16383;
    int hcol = rem2 >> 8;
    int d = rem2 & 255;
    const float* W = (z == 0) ? W2A : (z == 1) ? W2S : W2B;
    float v = W[e * 16384 + hcol * 256 + d];
    __nv_bfloat16 h = __float2bfloat16(v);
    g_w2h[z * 4 + e][d * 64 + hcol] = h;
    g_w2l[z * 4 + e][d * 64 + hcol] = __float2bfloat16(v - __bfloat162float(h));
}

// ---------------------------------------------------------------------------
// xsplit_gates: stream x once; emit xh/xl bf16 and gate softmax.
// 4 rows per warp: Wg smem loads amortized 4x.
// ---------------------------------------------------------------------------
template <int G>
__device__ __forceinline__ void xsg_row4(
    const float* __restrict__ X, __nv_bfloat16* __restrict__ XH,
    __nv_bfloat16* __restrict__ XL, const float* __restrict__ wT,
    const float* __restrict__ bg, float* __restrict__ gout,
    int row0, int lane)
{
    float acc[4][G];
    #pragma unroll
    for (int r = 0; r < 4; r++)
        #pragma unroll
        for (int g = 0; g < G; g++) acc[r][g] = 0.f;

    #pragma unroll
    for (int j = 0; j < 8; j++) {
        int f0 = j * 128 + lane * 4;
        float4 xv[4];
        #pragma unroll
        for (int r = 0; r < 4; r++) {
            size_t off = (size_t)(row0 + r) * FDIM + f0;
            xv[r] = *(const float4*)(X + off);
            uint32_t h0, h1, l0, l1;
            split2(xv[r].x, xv[r].y, h0, l0);
            split2(xv[r].z, xv[r].w, h1, l1);
            *(uint2*)(XH + off) = make_uint2(h0, h1);
            *(uint2*)(XL + off) = make_uint2(l0, l1);
        }
        #pragma unroll
        for (int g = 0; g < G; g++) {
            float4 wv = *(const float4*)(wT + g * 1024 + f0);
            #pragma unroll
            for (int r = 0; r < 4; r++)
                acc[r][g] += xv[r].x * wv.x + xv[r].y * wv.y + xv[r].z * wv.z + xv[r].w * wv.w;
        }
    }
    #pragma unroll
    for (int r = 0; r < 4; r++)
        #pragma unroll
        for (int g = 0; g < G; g++) {
            #pragma unroll
            for (int o = 16; o > 0; o >>= 1)
                acc[r][g] += __shfl_xor_sync(0xffffffffu, acc[r][g], o);
        }
    if (lane == 0) {
        #pragma unroll
        for (int r = 0; r < 4; r++) {
            float l[G], m = -1e30f, s = 0.f;
            #pragma unroll
            for (int g = 0; g < G; g++) { l[g] = acc[r][g] + __ldg(&bg[g]); m = fmaxf(m, l[g]); }
            #pragma unroll
            for (int g = 0; g < G; g++) { l[g] = expf(l[g] - m); s += l[g]; }
            float inv = 1.f / s;
            #pragma unroll
            for (int g = 0; g < G; g++) gout[(size_t)(row0 + r) * G + g] = l[g] * inv;
        }
    }
}

__global__ __launch_bounds__(256) void xsplit_gates_kernel(
    const float* __restrict__ xA, const float* __restrict__ xS, const float* __restrict__ xB,
    const float* __restrict__ WgA, const float* __restrict__ WgS, const float* __restrict__ WgB,
    const float* __restrict__ bgA, const float* __restrict__ bgS, const float* __restrict__ bgB)
{
    extern __shared__ float wT[];
    int tid = threadIdx.x;
    int z = blockIdx.y;
    int G = (z == 1) ? 12 : 8;
    const float* X  = (z == 0) ? xA  : (z == 1) ? xS  : xB;
    const float* Wg = (z == 0) ? WgA : (z == 1) ? WgS : WgB;
    const float* bg = (z == 0) ? bgA : (z == 1) ? bgS : bgB;

    for (int i = tid; i < G * 1024; i += 256) {
        int f = i / G, g = i - f * G;
        wT[g * 1024 + f] = Wg[i];
    }
    __syncthreads();

    int wid = tid >> 5, lane = tid & 31;
    int row0 = blockIdx.x * 32 + wid * 4;

    if (z == 0)      xsg_row4<8 >(X, g_xh[0], g_xl[0], wT, bg, g_gA, row0, lane);
    else if (z == 1) xsg_row4<12>(X, g_xh[1], g_xl[1], wT, bg, g_gS, row0, lane);
    else             xsg_row4<8 >(X, g_xh[2], g_xl[2], wT, bg, g_gB, row0, lane);
}

// ---------------------------------------------------------------------------
// Phase 1: bf16-split GEMM via mma.sync m16n8k16.
// CTA tile M=128, N=128, K-chunk=32, hi/lo packed in one 128B smem row.
// MMA passes separated per product: D-reuse distance = 16 MMAs (was 1).
// ---------------------------------------------------------------------------
#define P1_STAGE 32768
#define P1_SMEM  (2 * P1_STAGE)

__global__ __launch_bounds__(256, 2) void phase1_mma_kernel(
    const float* __restrict__ b1A, const float* __restrict__ b1S, const float* __restrict__ b1B)
{
    extern __shared__ char smem[];
    uint32_t sb = smem_u32(smem);

    int tid  = threadIdx.x;
    int w    = tid >> 5;
    int lane = tid & 31;
    int wm   = w & 3;
    int wn   = w >> 2;
    int z    = blockIdx.z;
    int m0   = blockIdx.y * 128;
    int n0   = blockIdx.x * 128;

    const __nv_bfloat16* Xh = g_xh[z];
    const __nv_bfloat16* Xl = g_xl[z];
    const __nv_bfloat16* Wh = g_wh[z];
    const __nv_bfloat16* Wl = g_wl[z];
    const float* b1 = (z == 0) ? b1A : (z == 1) ? b1S : b1B;

    int trow[8], tsub[8], tpart[8];
    #pragma unroll
    for (int i = 0; i < 8; i++) {
        int task = i * 256 + tid;
        tpart[i] = task >> 10;
        int idx = task & 1023;
        trow[i] = idx >> 3;
        tsub[i] = idx & 7;
    }

    auto load_stage = [&](int s, int k0) {
        uint32_t base = sb + (uint32_t)s * P1_STAGE;
        #pragma unroll
        for (int i = 0; i < 8; i++) {
            int part = tpart[i], row = trow[i], sub = tsub[i];
            uint32_t dst = base + (uint32_t)part * 16384 + (uint32_t)(row * 128) +
                           (uint32_t)(((sub ^ (row & 7)) & 7) << 4);
            const __nv_bfloat16* src;
            int kof = (sub & 3) * 8;
            if (part == 0) src = ((sub < 4) ? Xh : Xl) + (size_t)(m0 + row) * FDIM + k0 + kof;
            else           src = ((sub < 4) ? Wh : Wl) + (size_t)(n0 + row) * FDIM + k0 + kof;
            cp16(dst, src);
        }
        cp_commit();
    };

    float D[2][8][4];
    #pragma unroll
    for (int mf = 0; mf < 2; mf++)
        #pragma unroll
        for (int nf = 0; nf < 8; nf++)
            #pragma unroll
            for (int k = 0; k < 4; k++) D[mf][nf][k] = 0.f;

    int q  = lane >> 3;
    int rr = lane & 7;

    load_stage(0, 0);

    for (int kc = 0; kc < 32; kc++) {
        int s = kc & 1;
        if (kc + 1 < 32) { load_stage(s ^ 1, (kc + 1) * 32); cp_wait<1>(); }
        else             { cp_wait<0>(); }
        __syncthreads();

        uint32_t sA = sb + (uint32_t)s * P1_STAGE;
        uint32_t sB = sA + 16384;

        #pragma unroll
        for (int kk = 0; kk < 2; kk++) {
            uint32_t Bh_[16], Bl_[16];
            #pragma unroll
            for (int bg = 0; bg < 4; bg++) {
                int rowb = wn * 64 + (bg * 2 + q / 2) * 8 + rr;
                int ch = kk * 2 + (q & 1);
                ldsm4(&Bh_[bg * 4], sB + (uint32_t)(rowb * 128 + ((ch ^ (rowb & 7)) << 4)));
                ldsm4(&Bl_[bg * 4], sB + (uint32_t)(rowb * 128 + (((ch + 4) ^ (rowb & 7)) << 4)));
            }
            uint32_t Af_[2][4];
            #pragma unroll
            for (int mf = 0; mf < 2; mf++) {
                int rowa = wm * 32 + mf * 16 + (q & 1) * 8 + rr;
                int ch = kk * 2 + (q >> 1);
                ldsm4(Af_[mf], sA + (uint32_t)(rowa * 128 + ((ch ^ (rowa & 7)) << 4)));
            }
            // pass 1: Ah * Bh (16 independent accumulators)
            #pragma unroll
            for (int mf = 0; mf < 2; mf++)
                #pragma unroll
                for (int nf = 0; nf < 8; nf++)
                    mma16816(D[mf][nf], Af_[mf], &Bh_[nf * 2]);
            // pass 2: Ah * Bl
            #pragma unroll
            for (int mf = 0; mf < 2; mf++)
                #pragma unroll
                for (int nf = 0; nf < 8; nf++)
                    mma16816(D[mf][nf], Af_[mf], &Bl_[nf * 2]);
            // reload A as lo-half
            #pragma unroll
            for (int mf = 0; mf < 2; mf++) {
                int rowa = wm * 32 + mf * 16 + (q & 1) * 8 + rr;
                int ch = kk * 2 + (q >> 1) + 4;
                ldsm4(Af_[mf], sA + (uint32_t)(rowa * 128 + ((ch ^ (rowa & 7)) << 4)));
            }
            // pass 3: Al * Bh
            #pragma unroll
            for (int mf = 0; mf < 2; mf++)
                #pragma unroll
                for (int nf = 0; nf < 8; nf++)
                    mma16816(D[mf][nf], Af_[mf], &Bh_[nf * 2]);
        }
        __syncthreads();
    }

    // Epilogue: bias + relu -> bf16-split h
    __nv_bfloat16* Hh = g_hh[z];
    __nv_bfloat16* Hl = g_hl[z];
    #pragma unroll
    for (int nf = 0; nf < 8; nf++) {
        int col = n0 + wn * 64 + nf * 8 + (lane & 3) * 2;
        float bias0 = __ldg(&b1[col]);
        float bias1 = __ldg(&b1[col + 1]);
        #pragma unroll
        for (int mf = 0; mf < 2; mf++) {
            int row0 = m0 + wm * 32 + mf * 16 + (lane >> 2);
            float v00 = fmaxf(D[mf][nf][0] + bias0, 0.f);
            float v01 = fmaxf(D[mf][nf][1] + bias1, 0.f);
            float v10 = fmaxf(D[mf][nf][2] + bias0, 0.f);
            float v11 = fmaxf(D[mf][nf][3] + bias1, 0.f);
            uint32_t h0, l0, h1, l1;
            split2(v00, v01, h0, l0);
            split2(v10, v11, h1, l1);
            *(uint32_t*)(Hh + (size_t)row0 * NH + col)       = h0;
            *(uint32_t*)(Hl + (size_t)row0 * NH + col)       = l0;
            *(uint32_t*)(Hh + (size_t)(row0 + 8) * NH + col) = h1;
            *(uint32_t*)(Hl + (size_t)(row0 + 8) * NH + col) = l1;
        }
    }
}

// ---------------------------------------------------------------------------
// Phase 2: bf16-split mma.sync over experts, fused gate-weighted combine.
// grid = (BSZ/64, 6). MMA passes separated per product (y-reuse distance 8).
// ---------------------------------------------------------------------------
#define SG_HH  0
#define SG_HL  8192
#define SG_WH  16384
#define SG_WL  32768
#define SG_B2  49152
#define STG2   49664
#define GS_OFF (2 * STG2)
#define P2_SMEM (GS_OFF + 64 * 12 * 4)   // 102400

__global__ __launch_bounds__(256, 2) void phase2_mma_kernel(
    const float* __restrict__ b2A, const float* __restrict__ b2S, const float* __restrict__ b2B,
    float* __restrict__ out)
{
    extern __shared__ char smem[];
    uint32_t sb = smem_u32(smem);
    float* gs = (float*)(smem + GS_OFF);

    int tid  = threadIdx.x;
    int w    = tid >> 5;
    int lane = tid & 31;
    int wm   = w >> 2;        // 0..1 (m-tiles of 32)
    int wn   = w & 3;         // 0..3 (n-tiles of 32)
    int o      = blockIdx.y >> 1;   // output: 0=A, 1=S, 2=B
    int nhalf  = blockIdx.y & 1;    // which 128-col half of D
    int m0   = blockIdx.x * 64;
    int Ecnt = (o == 1) ? 12 : 8;

    // gate staging: gs[64][12]
    {
        int G = (o == 1) ? 12 : 8;
        const float* gsrc = (o == 0) ? g_gA : (o == 1) ? g_gS : g_gB;
        for (int t = tid; t < 64 * 12; t += 256) {
            int r = t / 12, c = t - r * 12;
            if (c < G) gs[t] = gsrc[(size_t)(m0 + r) * G + c];
        }
    }

    auto z_of = [&](int ei) -> int {
        if (o == 0) return ei < 4 ? 0 : 1;
        if (o == 1) return ei >> 2;
        return ei < 4 ? 2 : 1;
    };

    auto load_stage = [&](int s, int ei) {
        int z = z_of(ei);
        int e = ei & 3;
        const __nv_bfloat16* Hh = g_hh[z];
        const __nv_bfloat16* Hl = g_hl[z];
        const __nv_bfloat16* Wh = g_w2h[z * 4 + e] + nhalf * 128 * 64;
        const __nv_bfloat16* Wl = g_w2l[z * 4 + e] + nhalf * 128 * 64;
        const float* b2 = ((z == 0) ? b2A : (z == 1) ? b2S : b2B) + e * DDIM + nhalf * 128;
        uint32_t base = sb + (uint32_t)s * STG2;
        for (int i = tid; i < 3104; i += 256) {
            if (i < 1024) {
                int part = i >> 9;        // 0=Hh 1=Hl
                int idx = i & 511;
                int row = idx >> 3, sub = idx & 7;
                uint32_t dst = base + (part ? SG_HL : SG_HH) + (uint32_t)(row * 128) +
                               (uint32_t)(((sub ^ (row & 7)) & 7) << 4);
                const __nv_bfloat16* src = (part ? Hl : Hh) +
                    (size_t)(m0 + row) * NH + e * 64 + sub * 8;
                cp16(dst, src);
            } else if (i < 3072) {
                int j = i - 1024;
                int part = j >> 10;       // 0=Wh 1=Wl
                int idx = j & 1023;
                int row = idx >> 3, sub = idx & 7;
                uint32_t dst = base + (part ? SG_WL : SG_WH) + (uint32_t)(row * 128) +
                               (uint32_t)(((sub ^ (row & 7)) & 7) << 4);
                const __nv_bfloat16* src = (part ? Wl : Wh) + row * 64 + sub * 8;
                cp16(dst, src);
            } else {
                int idx = i - 3072;       // 32 chunks of b2 (128 floats)
                cp16(base + SG_B2 + (uint32_t)(idx * 16), b2 + idx * 4);
            }
        }
        cp_commit();
    };

    float acc[2][4][4];
    #pragma unroll
    for (int mf = 0; mf < 2; mf++)
        #pragma unroll
        for (int nf = 0; nf < 4; nf++)
            #pragma unroll
            for (int k = 0; k < 4; k++) acc[mf][nf][k] = 0.f;

    int q  = lane >> 3;
    int rr = lane & 7;

    load_stage(0, 0);

    for (int ei = 0; ei < Ecnt; ei++) {
        int s = ei & 1;
        if (ei + 1 < Ecnt) { load_stage(s ^ 1, ei + 1); cp_wait<1>(); }
        else               { cp_wait<0>(); }
        __syncthreads();

        uint32_t sHh = sb + (uint32_t)s * STG2 + SG_HH;
        uint32_t sHl = sHh + 8192;
        uint32_t sWh = sb + (uint32_t)s * STG2 + SG_WH;
        uint32_t sWl = sb + (uint32_t)s * STG2 + SG_WL;
        const float* b2s = (const float*)(smem + s * STG2 + SG_B2);

        float y[2][4][4];
        #pragma unroll
        for (int mf = 0; mf < 2; mf++)
            #pragma unroll
            for (int nf = 0; nf < 4; nf++)
                #pragma unroll
                for (int k = 0; k < 4; k++) y[mf][nf][k] = 0.f;

        #pragma unroll
        for (int kk = 0; kk < 4; kk++) {
            uint32_t Bh_[8], Bl_[8];
            #pragma unroll
            for (int bg = 0; bg < 2; bg++) {
                int rowb = wn * 32 + (bg * 2 + q / 2) * 8 + rr;
                int ch = kk * 2 + (q & 1);
                uint32_t off = (uint32_t)(rowb * 128 + ((ch ^ (rowb & 7)) << 4));
                ldsm4(&Bh_[bg * 4], sWh + off);
                ldsm4(&Bl_[bg * 4], sWl + off);
            }
            uint32_t Af_[2][4];
            #pragma unroll
            for (int mf = 0; mf < 2; mf++) {
                int rowa = wm * 32 + mf * 16 + (q & 1) * 8 + rr;
                int ch = kk * 2 + (q >> 1);
                uint32_t off = (uint32_t)(rowa * 128 + ((ch ^ (rowa & 7)) << 4));
                ldsm4(Af_[mf], sHh + off);
            }
            // pass 1: Hh * Wh
            #pragma unroll
            for (int mf = 0; mf < 2; mf++)
                #pragma unroll
                for (int nf = 0; nf < 4; nf++)
                    mma16816(y[mf][nf], Af_[mf], &Bh_[nf * 2]);
            // pass 2: Hh * Wl
            #pragma unroll
            for (int mf = 0; mf < 2; mf++)
                #pragma unroll
                for (int nf = 0; nf < 4; nf++)
                    mma16816(y[mf][nf], Af_[mf], &Bl_[nf * 2]);
            // reload H as lo-half
            #pragma unroll
            for (int mf = 0; mf < 2; mf++) {
                int rowa = wm * 32 + mf * 16 + (q & 1) * 8 + rr;
                int ch = kk * 2 + (q >> 1);
                uint32_t off = (uint32_t)(rowa * 128 + ((ch ^ (rowa & 7)) << 4));
                ldsm4(Af_[mf], sHl + off);
            }
            // pass 3: Hl * Wh
            #pragma unroll
            for (int mf = 0; mf < 2; mf++)
                #pragma unroll
                for (int nf = 0; nf < 4; nf++)
                    mma16816(y[mf][nf], Af_[mf], &Bh_[nf * 2]);
        }

        // gate-weighted relu accumulation (fragment layout)
        #pragma unroll
        for (int mf = 0; mf < 2; mf++) {
            int r0 = wm * 32 + mf * 16 + (lane >> 2);
            float g0 = gs[r0 * 12 + ei];
            float g1 = gs[(r0 + 8) * 12 + ei];
            #pragma unroll
            for (int nf = 0; nf < 4; nf++) {
                int c0 = wn * 32 + nf * 8 + (lane & 3) * 2;
                float bb0 = b2s[c0];
                float bb1 = b2s[c0 + 1];
                acc[mf][nf][0] = fmaf(g0, fmaxf(y[mf][nf][0] + bb0, 0.f), acc[mf][nf][0]);
                acc[mf][nf][1] = fmaf(g0, fmaxf(y[mf][nf][1] + bb1, 0.f), acc[mf][nf][1]);
                acc[mf][nf][2] = fmaf(g1, fmaxf(y[mf][nf][2] + bb0, 0.f), acc[mf][nf][2]);
                acc[mf][nf][3] = fmaf(g1, fmaxf(y[mf][nf][3] + bb1, 0.f), acc[mf][nf][3]);
            }
        }
        __syncthreads();
    }

    // write output
    float* obase = out + (size_t)o * BD + nhalf * 128;
    #pragma unroll
    for (int mf = 0; mf < 2; mf++) {
        int r0 = m0 + wm * 32 + mf * 16 + (lane >> 2);
        #pragma unroll
        for (int nf = 0; nf < 4; nf++) {
            int c0 = wn * 32 + nf * 8 + (lane & 3) * 2;
            *(float2*)(obase + (size_t)r0 * DDIM + c0)       = make_float2(acc[mf][nf][0], acc[mf][nf][1]);
            *(float2*)(obase + (size_t)(r0 + 8) * DDIM + c0) = make_float2(acc[mf][nf][2], acc[mf][nf][3]);
        }
    }
}

// ---------------------------------------------------------------------------
extern "C" void kernel_launch(void* const* d_in, const int* in_sizes, int n_in,
                              void* d_out, int out_size)
{
    const float* xA  = (const float*)d_in[0];
    const float* xS  = (const float*)d_in[1];
    const float* xB  = (const float*)d_in[2];
    const float* W1A = (const float*)d_in[3];
    const float* b1A = (const float*)d_in[4];
    const float* W2A = (const float*)d_in[5];
    const float* b2A = (const float*)d_in[6];
    const float* W1S = (const float*)d_in[7];
    const float* b1S = (const float*)d_in[8];
    const float* W2S = (const float*)d_in[9];
    const float* b2S = (const float*)d_in[10];
    const float* W1B = (const float*)d_in[11];
    const float* b1B = (const float*)d_in[12];
    const float* W2B = (const float*)d_in[13];
    const float* b2B = (const float*)d_in[14];
    const float* WgA = (const float*)d_in[15];
    const float* bgA = (const float*)d_in[16];
    const float* WgB = (const float*)d_in[17];
    const float* bgB = (const float*)d_in[18];
    const float* WgS = (const float*)d_in[19];
    const float* bgS = (const float*)d_in[20];
    float* out = (float*)d_out;

    cudaFuncSetAttribute(xsplit_gates_kernel, cudaFuncAttributeMaxDynamicSharedMemorySize, 12 * 1024 * 4);
    cudaFuncSetAttribute(phase1_mma_kernel,   cudaFuncAttributeMaxDynamicSharedMemorySize, P1_SMEM);
    cudaFuncSetAttribute(phase2_mma_kernel,   cudaFuncAttributeMaxDynamicSharedMemorySize, P2_SMEM);

    wsplit_kernel<<<3072, 256>>>(W1A, W1S, W1B);
    w2split_kernel<<<768, 256>>>(W2A, W2S, W2B);
    xsplit_gates_kernel<<<dim3(512, 3), 256, 12 * 1024 * 4>>>(xA, xS, xB, WgA, WgS, WgB, bgA, bgS, bgB);
    phase1_mma_kernel<<<dim3(2, 128, 3), 256, P1_SMEM>>>(b1A, b1S, b1B);
    phase2_mma_kernel<<<dim3(BSZ / 64, 6), 256, P2_SMEM>>>(b2A, b2S, b2B, out);
}